// round 3
// baseline (speedup 1.0000x reference)
#include <cuda_runtime.h>

// TriMipEncoding: x [N,3] in [0,1], fm [3,512,512,16] fp32. out [N,48].
//
// R3: one thread per (point, channel-quad c). Thread gathers its float4 quad
// from all 4 texels of all 3 planes (12 LDG.128 in flight -> high MLP),
// loads x once, no integer division. Gather wavefronts stay at the structural
// minimum (1 line per texel); exposed latency shrinks.

#define PLANE 512

__global__ void __launch_bounds__(256) trimip_kernel(
    const float* __restrict__ x,
    const float4* __restrict__ fm4,
    float4* __restrict__ out4,
    int n_pts)
{
    int idx = blockIdx.x * blockDim.x + threadIdx.x;
    int n = idx >> 2;       // point
    int c = idx & 3;        // channel quad 0..3
    if (n >= n_pts) return;

    float x0 = __ldg(x + n * 3 + 0);
    float x1 = __ldg(x + n * 3 + 1);
    float x2 = __ldg(x + n * 3 + 2);

    // plane 0: (y,z) ; plane 1: (x,z) ; plane 2: (x,y)
    float us[3] = { x1, x0, x0 };
    float vs[3] = { x2, x2, x1 };

    float w00[3], w01[3], w10[3], w11[3];
    const float4* a00[3]; const float4* a01[3];
    const float4* a10[3]; const float4* a11[3];

    #pragma unroll
    for (int p = 0; p < 3; p++) {
        float u = us[p] * (float)PLANE - 0.5f;
        float v = vs[p] * (float)PLANE - 0.5f;
        float i0f = floorf(u);
        float j0f = floorf(v);
        float fu = u - i0f;
        float fv = v - j0f;

        int i0 = min(max((int)i0f,     0), PLANE - 1);
        int i1 = min(max((int)i0f + 1, 0), PLANE - 1);
        int j0 = min(max((int)j0f,     0), PLANE - 1);
        int j1 = min(max((int)j0f + 1, 0), PLANE - 1);

        w00[p] = (1.0f - fv) * (1.0f - fu);
        w01[p] = (1.0f - fv) * fu;
        w10[p] = fv * (1.0f - fu);
        w11[p] = fv * fu;

        // texel (p,j,i) quad c: float4 index ((p*512 + j)*512 + i)*4 + c
        const float4* base = fm4 + ((size_t)p << 20) + c;   // 512*512*4 = 1<<20
        size_t r0 = (size_t)j0 * (PLANE * 4);
        size_t r1 = (size_t)j1 * (PLANE * 4);
        a00[p] = base + r0 + (size_t)i0 * 4;
        a01[p] = base + r0 + (size_t)i1 * 4;
        a10[p] = base + r1 + (size_t)i0 * 4;
        a11[p] = base + r1 + (size_t)i1 * 4;
    }

    // Issue all 12 gathers (compiler front-batches -> MLP 12)
    float4 v00[3], v01[3], v10[3], v11[3];
    #pragma unroll
    for (int p = 0; p < 3; p++) {
        v00[p] = __ldg(a00[p]);
        v01[p] = __ldg(a01[p]);
        v10[p] = __ldg(a10[p]);
        v11[p] = __ldg(a11[p]);
    }

    #pragma unroll
    for (int p = 0; p < 3; p++) {
        float4 r;
        r.x = w00[p] * v00[p].x + w01[p] * v01[p].x + w10[p] * v10[p].x + w11[p] * v11[p].x;
        r.y = w00[p] * v00[p].y + w01[p] * v01[p].y + w10[p] * v10[p].y + w11[p] * v11[p].y;
        r.z = w00[p] * v00[p].z + w01[p] * v01[p].z + w10[p] * v10[p].z + w11[p] * v11[p].z;
        r.w = w00[p] * v00[p].w + w01[p] * v01[p].w + w10[p] * v10[p].w + w11[p] * v11[p].w;
        out4[(size_t)n * 12 + p * 4 + c] = r;
    }
}

extern "C" void kernel_launch(void* const* d_in, const int* in_sizes, int n_in,
                              void* d_out, int out_size)
{
    const float*  x   = (const float*)d_in[0];    // [N,3]
    const float4* fm4 = (const float4*)d_in[1];   // [3,512,512,16] as float4
    float4* out4 = (float4*)d_out;                // [N,48] as float4

    int n_pts = in_sizes[0] / 3;
    int total = n_pts * 4;
    int threads = 256;
    int blocks = (total + threads - 1) / threads;
    trimip_kernel<<<blocks, threads>>>(x, fm4, out4, n_pts);
}

// round 5
// speedup vs baseline: 1.0332x; 1.0332x over previous
#include <cuda_runtime.h>

// TriMipEncoding: x [N,3] in [0,1], fm [3,512,512,16] fp32. out [N,48].
//
// R5 = R2 structure (4 threads per (point,plane), one float4 channel-quad
// each — measured best) + L2 residency hygiene, now via the ptxas-accepted
// createpolicy + L2::cache_hint form:
//   - fm gathers:  ld.global.nc.L2::cache_hint (policy = evict_last, frac 1.0)
//   - out stores:  __stcs (evict-first; write stream stops thrashing fm)
//   - x loads:     __ldcs (streamed, read-once per pass)

#define PLANE_H 512
#define PLANE_W 512

__device__ __forceinline__ float4 ldg_resident(const float4* p, unsigned long long pol) {
    float4 v;
    asm("ld.global.nc.L2::cache_hint.v4.f32 {%0,%1,%2,%3}, [%4], %5;"
        : "=f"(v.x), "=f"(v.y), "=f"(v.z), "=f"(v.w)
        : "l"(p), "l"(pol));
    return v;
}

__global__ void __launch_bounds__(256) trimip_kernel(
    const float* __restrict__ x,
    const float4* __restrict__ fm4,
    float4* __restrict__ out4,
    int total)   // = n_pts * 12
{
    int idx = blockIdx.x * blockDim.x + threadIdx.x;
    if (idx >= total) return;

    // L2 policy: keep fm resident (evict_last on 100% of accesses)
    unsigned long long pol;
    asm("createpolicy.fractional.L2::evict_last.b64 %0, 1.0;" : "=l"(pol));

    int c = idx & 3;        // channel quad 0..3
    int t = idx >> 2;       // (point, plane)
    int n = t / 3;
    int p = t - n * 3;

    // Point coords: 12 threads per point read the same 3 floats.
    float x0 = __ldcs(x + n * 3 + 0);
    float x1 = __ldcs(x + n * 3 + 1);
    float x2 = __ldcs(x + n * 3 + 2);

    // plane 0: (y,z) ; plane 1: (x,z) ; plane 2: (x,y)
    float cu = (p == 0) ? x1 : x0;
    float cv = (p == 2) ? x1 : x2;

    float u = cu * (float)PLANE_W - 0.5f;
    float v = cv * (float)PLANE_H - 0.5f;
    float i0f = floorf(u);
    float j0f = floorf(v);
    float fu = u - i0f;
    float fv = v - j0f;

    int i0 = min(max((int)i0f,     0), PLANE_W - 1);
    int i1 = min(max((int)i0f + 1, 0), PLANE_W - 1);
    int j0 = min(max((int)j0f,     0), PLANE_H - 1);
    int j1 = min(max((int)j0f + 1, 0), PLANE_H - 1);

    float w00 = (1.0f - fv) * (1.0f - fu);
    float w01 = (1.0f - fv) * fu;
    float w10 = fv * (1.0f - fu);
    float w11 = fv * fu;

    // float4 index of texel (j,i) in plane p, channel quad c:
    //   ((p*H + j)*W + i)*4 + c
    size_t plane_base = (size_t)p * PLANE_H * PLANE_W * 4 + c;
    size_t r0 = plane_base + (size_t)j0 * (PLANE_W * 4);
    size_t r1 = plane_base + (size_t)j1 * (PLANE_W * 4);

    float4 a = ldg_resident(fm4 + r0 + (size_t)i0 * 4, pol);
    float4 b = ldg_resident(fm4 + r0 + (size_t)i1 * 4, pol);
    float4 d = ldg_resident(fm4 + r1 + (size_t)i0 * 4, pol);
    float4 e = ldg_resident(fm4 + r1 + (size_t)i1 * 4, pol);

    float4 r;
    r.x = w00 * a.x + w01 * b.x + w10 * d.x + w11 * e.x;
    r.y = w00 * a.y + w01 * b.y + w10 * d.y + w11 * e.y;
    r.z = w00 * a.z + w01 * b.z + w10 * d.z + w11 * e.z;
    r.w = w00 * a.w + w01 * b.w + w10 * d.w + w11 * e.w;

    // out float4 index = n*12 + p*4 + c = idx (dense, coalesced); streaming store
    __stcs(out4 + idx, r);
}

extern "C" void kernel_launch(void* const* d_in, const int* in_sizes, int n_in,
                              void* d_out, int out_size)
{
    const float*  x   = (const float*)d_in[0];    // [N,3]
    const float4* fm4 = (const float4*)d_in[1];   // [3,512,512,16] as float4
    float4* out4 = (float4*)d_out;                // [N,48] as float4

    int n_pts = in_sizes[0] / 3;
    int total = n_pts * 12;
    int threads = 256;
    int blocks = (total + threads - 1) / threads;
    trimip_kernel<<<blocks, threads>>>(x, fm4, out4, total);
}

// round 6
// speedup vs baseline: 1.2006x; 1.1620x over previous
#include <cuda_runtime.h>

// TriMipEncoding: x [N,3] in [0,1], fm [3,512,512,16] fp32. out [N,48].
//
// R6 = R2 memory shape (thread owns one float4 channel-quad of one
// (point,plane); gathers 4 texel-quads) but each thread handles TWO units
// (idx, idx + T/2) with all 8 LDG.128 front-batched -> MLP 8/thread,
// ~270 outstanding loads/SM, hiding L2-hit latency that R2 left exposed.
// Keeps L2 evict_last on fm + streaming stores.

#define PLANE_H 512
#define PLANE_W 512

__device__ __forceinline__ float4 ldg_resident(const float4* p, unsigned long long pol) {
    float4 v;
    asm("ld.global.nc.L2::cache_hint.v4.f32 {%0,%1,%2,%3}, [%4], %5;"
        : "=f"(v.x), "=f"(v.y), "=f"(v.z), "=f"(v.w)
        : "l"(p), "l"(pol));
    return v;
}

struct Unit {
    const float4* a00; const float4* a01; const float4* a10; const float4* a11;
    float w00, w01, w10, w11;
};

__device__ __forceinline__ Unit decode(int idx, const float* __restrict__ x,
                                        const float4* __restrict__ fm4) {
    Unit un;
    int c = idx & 3;
    int t = idx >> 2;
    int n = t / 3;           // magic-mul, no trap
    int p = t - n * 3;

    float x0 = __ldg(x + n * 3 + 0);
    float x1 = __ldg(x + n * 3 + 1);
    float x2 = __ldg(x + n * 3 + 2);

    float cu = (p == 0) ? x1 : x0;
    float cv = (p == 2) ? x1 : x2;

    float u = cu * (float)PLANE_W - 0.5f;
    float v = cv * (float)PLANE_H - 0.5f;
    float i0f = floorf(u);
    float j0f = floorf(v);
    float fu = u - i0f;
    float fv = v - j0f;

    int i0 = min(max((int)i0f,     0), PLANE_W - 1);
    int i1 = min(max((int)i0f + 1, 0), PLANE_W - 1);
    int j0 = min(max((int)j0f,     0), PLANE_H - 1);
    int j1 = min(max((int)j0f + 1, 0), PLANE_H - 1);

    un.w00 = (1.0f - fv) * (1.0f - fu);
    un.w01 = (1.0f - fv) * fu;
    un.w10 = fv * (1.0f - fu);
    un.w11 = fv * fu;

    size_t plane_base = (size_t)p * PLANE_H * PLANE_W * 4 + c;
    size_t r0 = plane_base + (size_t)j0 * (PLANE_W * 4);
    size_t r1 = plane_base + (size_t)j1 * (PLANE_W * 4);
    un.a00 = fm4 + r0 + (size_t)i0 * 4;
    un.a01 = fm4 + r0 + (size_t)i1 * 4;
    un.a10 = fm4 + r1 + (size_t)i0 * 4;
    un.a11 = fm4 + r1 + (size_t)i1 * 4;
    return un;
}

__device__ __forceinline__ float4 blend(const Unit& un,
                                        float4 a, float4 b, float4 d, float4 e) {
    float4 r;
    r.x = un.w00 * a.x + un.w01 * b.x + un.w10 * d.x + un.w11 * e.x;
    r.y = un.w00 * a.y + un.w01 * b.y + un.w10 * d.y + un.w11 * e.y;
    r.z = un.w00 * a.z + un.w01 * b.z + un.w10 * d.z + un.w11 * e.z;
    r.w = un.w00 * a.w + un.w01 * b.w + un.w10 * d.w + un.w11 * e.w;
    return r;
}

__global__ void __launch_bounds__(128) trimip_kernel(
    const float* __restrict__ x,
    const float4* __restrict__ fm4,
    float4* __restrict__ out4,
    int half)   // = n_pts * 6 ; unit1 = idx + half
{
    int idx = blockIdx.x * blockDim.x + threadIdx.x;
    if (idx >= half) return;

    unsigned long long pol;
    asm("createpolicy.fractional.L2::evict_last.b64 %0, 1.0;" : "=l"(pol));

    Unit u0 = decode(idx,        x, fm4);
    Unit u1 = decode(idx + half, x, fm4);

    // Front-batch all 8 gathers (MLP = 8)
    float4 a0 = ldg_resident(u0.a00, pol);
    float4 b0 = ldg_resident(u0.a01, pol);
    float4 d0 = ldg_resident(u0.a10, pol);
    float4 e0 = ldg_resident(u0.a11, pol);
    float4 a1 = ldg_resident(u1.a00, pol);
    float4 b1 = ldg_resident(u1.a01, pol);
    float4 d1 = ldg_resident(u1.a10, pol);
    float4 e1 = ldg_resident(u1.a11, pol);

    __stcs(out4 + idx,        blend(u0, a0, b0, d0, e0));
    __stcs(out4 + idx + half, blend(u1, a1, b1, d1, e1));
}

extern "C" void kernel_launch(void* const* d_in, const int* in_sizes, int n_in,
                              void* d_out, int out_size)
{
    const float*  x   = (const float*)d_in[0];    // [N,3]
    const float4* fm4 = (const float4*)d_in[1];   // [3,512,512,16] as float4
    float4* out4 = (float4*)d_out;                // [N,48] as float4

    int n_pts = in_sizes[0] / 3;
    int half = n_pts * 6;                          // n_pts*12 / 2
    int threads = 128;
    int blocks = (half + threads - 1) / threads;
    trimip_kernel<<<blocks, threads>>>(x, fm4, out4, half);
}